// round 14
// baseline (speedup 1.0000x reference)
#include <cuda_runtime.h>
#include <cuda_fp16.h>
#include <cstdint>
#include <math.h>

#define BATCH 2
#define SEQ   2048
#define DMODEL 1024
#define NHEADS 16
#define DK    64
#define MROWS (BATCH*SEQ)   // 4096

// ---------------------------------------------------------------------------
// Scratch (fp16 operands + intermediates)
// ---------------------------------------------------------------------------
__device__ __align__(128) __half g_Qh[MROWS * DMODEL];
__device__ __align__(128) __half g_Kh[MROWS * DMODEL];
__device__ __align__(128) __half g_Vh[MROWS * DMODEL];
__device__ __align__(128) __half g_Oh[MROWS * DMODEL];
__device__ __align__(128) __half g_Xq[MROWS * DMODEL];
__device__ __align__(128) __half g_Xk[MROWS * DMODEL];
__device__ __align__(128) __half g_Xv[MROWS * DMODEL];
__device__ __align__(128) __half g_Wq[DMODEL * DMODEL];
__device__ __align__(128) __half g_Wk[DMODEL * DMODEL];
__device__ __align__(128) __half g_Wv[DMODEL * DMODEL];
__device__ __align__(128) __half g_Wo[DMODEL * DMODEL];

__device__ __forceinline__ uint32_t smem_u32(const void* p) {
    uint32_t a;
    asm("{ .reg .u64 t; cvta.to.shared.u64 t, %1; cvt.u32.u64 %0, t; }" : "=r"(a) : "l"(p));
    return a;
}
__device__ __forceinline__ void cp16(uint32_t dst, const void* src) {
    asm volatile("cp.async.cg.shared.global [%0], [%1], 16;" :: "r"(dst), "l"(src));
}
#define CP_COMMIT() asm volatile("cp.async.commit_group;" ::: "memory")
#define CP_WAIT(n)  asm volatile("cp.async.wait_group %0;" :: "n"(n) : "memory")

__device__ __forceinline__ void ldsm4(uint32_t* r, uint32_t a) {
    asm volatile("ldmatrix.sync.aligned.m8n8.x4.shared.b16 {%0,%1,%2,%3}, [%4];"
        : "=r"(r[0]), "=r"(r[1]), "=r"(r[2]), "=r"(r[3]) : "r"(a));
}
__device__ __forceinline__ void ldsm4t(uint32_t* r, uint32_t a) {
    asm volatile("ldmatrix.sync.aligned.m8n8.x4.trans.shared.b16 {%0,%1,%2,%3}, [%4];"
        : "=r"(r[0]), "=r"(r[1]), "=r"(r[2]), "=r"(r[3]) : "r"(a));
}
__device__ __forceinline__ float ex2a(float x) {
    float y; asm("ex2.approx.ftz.f32 %0, %1;" : "=f"(y) : "f"(x));
    return y;
}
#define MMA_F16(d, a, b0, b1) \
    asm volatile( \
        "mma.sync.aligned.m16n8k16.row.col.f32.f16.f16.f32 " \
        "{%0,%1,%2,%3}, {%4,%5,%6,%7}, {%8,%9}, {%0,%1,%2,%3};" \
        : "+f"((d)[0]), "+f"((d)[1]), "+f"((d)[2]), "+f"((d)[3]) \
        : "r"((a)[0]), "r"((a)[1]), "r"((a)[2]), "r"((a)[3]), "r"(b0), "r"(b1))

// Q pre-scale: 1/sqrt(64) * log2(e)  (softmax in base 2)
#define QSCALE (0.125f * 1.44269504088896f)

// ---------------------------------------------------------------------------
// Pre-pass: fp32 -> fp16 (rn) into scratch (inputs + weights).
// ---------------------------------------------------------------------------
__global__ __launch_bounds__(256) void prepass(
    const float* __restrict__ q, const float* __restrict__ k, const float* __restrict__ v,
    const float* __restrict__ Wq, const float* __restrict__ Wk,
    const float* __restrict__ Wv, const float* __restrict__ Wo)
{
    const float* src; __half* dst; int n8;
    switch (blockIdx.y) {
        case 0: src = q;  dst = g_Xq; n8 = MROWS * DMODEL / 8; break;
        case 1: src = k;  dst = g_Xk; n8 = MROWS * DMODEL / 8; break;
        case 2: src = v;  dst = g_Xv; n8 = MROWS * DMODEL / 8; break;
        case 3: src = Wq; dst = g_Wq; n8 = DMODEL * DMODEL / 8; break;
        case 4: src = Wk; dst = g_Wk; n8 = DMODEL * DMODEL / 8; break;
        case 5: src = Wv; dst = g_Wv; n8 = DMODEL * DMODEL / 8; break;
        default: src = Wo; dst = g_Wo; n8 = DMODEL * DMODEL / 8; break;
    }
    for (int i = blockIdx.x * blockDim.x + threadIdx.x; i < n8; i += gridDim.x * blockDim.x) {
        float4 t0 = reinterpret_cast<const float4*>(src)[2 * i];
        float4 t1 = reinterpret_cast<const float4*>(src)[2 * i + 1];
        uint4 u;
        __half2 h;
        h = __floats2half2_rn(t0.x, t0.y); u.x = *reinterpret_cast<uint32_t*>(&h);
        h = __floats2half2_rn(t0.z, t0.w); u.y = *reinterpret_cast<uint32_t*>(&h);
        h = __floats2half2_rn(t1.x, t1.y); u.z = *reinterpret_cast<uint32_t*>(&h);
        h = __floats2half2_rn(t1.z, t1.w); u.w = *reinterpret_cast<uint32_t*>(&h);
        reinterpret_cast<uint4*>(dst)[i] = u;
    }
}

// ---------------------------------------------------------------------------
// FP16 mma GEMM (NT) — exact R10 shape: 3-stage, CP_WAIT(1), late issue.
// CTA 128x128, 8 warps of 64x32, K-chunk 32, ldmatrix.
// mode: 0 = fp32 out, 1 = fp16 out, 2 = fp16 out * QSCALE
// ---------------------------------------------------------------------------
#define GBM 128
#define GBN 128
#define GBK 32
#define GSTR 40
#define GTILE_H (128 * GSTR)
#define GSTG 3
#define GEMM_SMEM (GSTG * 2 * GTILE_H * 2)  // 61440 B

__device__ __forceinline__ void gemm_f16_body(
    const __half* __restrict__ A, const __half* __restrict__ B,
    const float* __restrict__ bias, float* __restrict__ Cf, __half* __restrict__ Ch,
    int mode)
{
    extern __shared__ __half smh[];
    __half* As = smh;
    __half* Bs = smh + GSTG * GTILE_H;

    const int t    = threadIdx.x;
    const int wid  = t >> 5;
    const int lane = t & 31;
    const int l7   = lane & 7;
    const int l8   = (lane >> 3) & 1;
    const int l16  = lane >> 4;
    const int lq   = lane >> 2;
    const int lr4  = lane & 3;
    const int mbase = blockIdx.y * GBM;
    const int nbase = blockIdx.x * GBN;

    const int srow = t >> 1, sseg = (t & 1) * 16;
    const __half* Ap = A + (size_t)(mbase + srow) * DMODEL + sseg;
    const __half* Bp = B + (size_t)(nbase + srow) * DMODEL + sseg;
    const uint32_t a_s = smem_u32(As) + (srow * GSTR + sseg) * 2;
    const uint32_t b_s = smem_u32(Bs) + (srow * GSTR + sseg) * 2;
    const uint32_t stb = GTILE_H * 2;

#define GI(c, s) { const __half* ap_ = Ap + (c) * GBK; \
        cp16(a_s + (s) * stb, ap_); cp16(a_s + (s) * stb + 16, ap_ + 8); \
        const __half* bp_ = Bp + (c) * GBK; \
        cp16(b_s + (s) * stb, bp_); cp16(b_s + (s) * stb + 16, bp_ + 8); }

    GI(0, 0); CP_COMMIT();
    GI(1, 1); CP_COMMIT();

    const int rm = (wid & 1) * 64;
    const int cn = (wid >> 1) * 32;
    const uint32_t laneA = ((l7 + 8 * l8) * GSTR + 8 * l16) * 2;
    const uint32_t laneB = ((l7 + 8 * l16) * GSTR + 8 * l8) * 2;

    float acc[4][4][4];
#pragma unroll
    for (int mt = 0; mt < 4; mt++)
#pragma unroll
        for (int nt = 0; nt < 4; nt++)
#pragma unroll
            for (int i = 0; i < 4; i++) acc[mt][nt][i] = 0.f;

    const int NCH = DMODEL / GBK;   // 32

    for (int c = 0; c < NCH; c++) {
        CP_WAIT(1);
        __syncthreads();
        const uint32_t sa = smem_u32(As) + (c % GSTG) * stb;
        const uint32_t sb = smem_u32(Bs) + (c % GSTG) * stb;
#pragma unroll
        for (int ks = 0; ks < 2; ks++) {
            const int k0 = ks * 16;
            uint32_t af[4][4], bf[2][4];
#pragma unroll
            for (int mt = 0; mt < 4; mt++)
                ldsm4(af[mt], sa + ((rm + mt * 16) * GSTR + k0) * 2 + laneA);
#pragma unroll
            for (int p = 0; p < 2; p++)
                ldsm4(bf[p], sb + ((cn + p * 16) * GSTR + k0) * 2 + laneB);
#pragma unroll
            for (int mt = 0; mt < 4; mt++)
#pragma unroll
                for (int nt = 0; nt < 4; nt++)
                    MMA_F16(acc[mt][nt], af[mt], bf[nt >> 1][(nt & 1) * 2],
                            bf[nt >> 1][(nt & 1) * 2 + 1]);
        }
        if (c + 2 < NCH) { GI(c + 2, (c + 2) % GSTG); }
        CP_COMMIT();
    }
#undef GI

#pragma unroll
    for (int mt = 0; mt < 4; mt++) {
        const int r0 = mbase + rm + mt * 16 + lq;
#pragma unroll
        for (int nt = 0; nt < 4; nt++) {
            const int col = nbase + cn + nt * 8 + lr4 * 2;
            const float bz0 = bias[col], bz1 = bias[col + 1];
            float v00 = acc[mt][nt][0] + bz0, v01 = acc[mt][nt][1] + bz1;
            float v10 = acc[mt][nt][2] + bz0, v11 = acc[mt][nt][3] + bz1;
            if (mode == 0) {
                *reinterpret_cast<float2*>(&Cf[(size_t)r0 * DMODEL + col]) = make_float2(v00, v01);
                *reinterpret_cast<float2*>(&Cf[(size_t)(r0 + 8) * DMODEL + col]) = make_float2(v10, v11);
            } else {
                if (mode == 2) { v00 *= QSCALE; v01 *= QSCALE; v10 *= QSCALE; v11 *= QSCALE; }
                *reinterpret_cast<__half2*>(&Ch[(size_t)r0 * DMODEL + col]) = __floats2half2_rn(v00, v01);
                *reinterpret_cast<__half2*>(&Ch[(size_t)(r0 + 8) * DMODEL + col]) = __floats2half2_rn(v10, v11);
            }
        }
    }
}

__global__ __launch_bounds__(256, 2) void gemm_qkv(
    const float* __restrict__ bq, const float* __restrict__ bk, const float* __restrict__ bv)
{
    const int z = blockIdx.z;
    const __half* A = (z == 0) ? g_Xq : (z == 1) ? g_Xk : g_Xv;
    const __half* B = (z == 0) ? g_Wq : (z == 1) ? g_Wk : g_Wv;
    const float* bi = (z == 0) ? bq   : (z == 1) ? bk   : bv;
    __half* C      = (z == 0) ? g_Qh : (z == 1) ? g_Kh : g_Vh;
    gemm_f16_body(A, B, bi, nullptr, C, (z == 0) ? 2 : 1);
}

__global__ __launch_bounds__(256, 2) void gemm_out(
    const float* __restrict__ bo, float* __restrict__ out)
{
    gemm_f16_body(g_Oh, g_Wo, bo, out, nullptr, 0);
}

// ---------------------------------------------------------------------------
// FP16 flash attention, P in registers.  Now 4 CTAs/SM (221KB/228KB smem).
// grid (16,16,2), block 128 (4 warps x 32 q-rows).
// ---------------------------------------------------------------------------
#define QT  128
#define KCH 64
#define ASTRH 72
#define AQ_OFF 0
#define AK_OFF (QT * ASTRH)
#define AV_OFF (AK_OFF + 2 * KCH * ASTRH)
#define ATTN_SMEM ((QT * ASTRH + 4 * KCH * ASTRH) * 2)  // 55296 B

__global__ __launch_bounds__(128, 4) void attn_f16()
{
    extern __shared__ __half sh[];
    __half* Qs = sh + AQ_OFF;
    __half* Ks = sh + AK_OFF;
    __half* Vs = sh + AV_OFF;

    const int t    = threadIdx.x;
    const int wid  = t >> 5;
    const int lane = t & 31;
    const int l7   = lane & 7;
    const int l8   = (lane >> 3) & 1;
    const int l16  = lane >> 4;

    const int qbase = blockIdx.x * QT;
    const int h     = blockIdx.y;
    const int b     = blockIdx.z;
    const int hbase = h * DK;

    {
        const __half* src = g_Qh + ((size_t)b * SEQ + qbase + t) * DMODEL + hbase;
        const uint32_t dst = smem_u32(Qs) + t * ASTRH * 2;
#pragma unroll
        for (int i = 0; i < 8; i++) cp16(dst + i * 16, src + i * 8);
        CP_COMMIT();
    }

    const int klr = t >> 1;
    const int klc = (t & 1) * 32;
    const uint32_t kvoff = (klr * ASTRH + klc) * 2;
    const uint32_t bufstride = KCH * ASTRH * 2;

#define ISSUE_KV(j0, buf) { \
        const size_t g_ = ((size_t)b * SEQ + (j0) + klr) * DMODEL + hbase + klc; \
        const __half* ks_ = g_Kh + g_; const __half* vs_ = g_Vh + g_; \
        const uint32_t kd_ = smem_u32(Ks) + (buf) * bufstride + kvoff; \
        const uint32_t vd_ = smem_u32(Vs) + (buf) * bufstride + kvoff; \
        cp16(kd_, ks_); cp16(kd_ + 16, ks_ + 8); cp16(kd_ + 32, ks_ + 16); cp16(kd_ + 48, ks_ + 24); \
        cp16(vd_, vs_); cp16(vd_ + 16, vs_ + 8); cp16(vd_ + 32, vs_ + 16); cp16(vd_ + 48, vs_ + 24); \
        CP_COMMIT(); }

    ISSUE_KV(0, 0);

    const int qr0 = wid * 32;
    const uint32_t laneA = ((l7 + 8 * l8) * ASTRH + 8 * l16) * 2;
    const uint32_t laneB = ((l7 + 8 * l16) * ASTRH + 8 * l8) * 2;
    const uint32_t qbase_s = smem_u32(Qs);

    float m[2][2], l[2][2];
#pragma unroll
    for (int mt = 0; mt < 2; mt++) { m[mt][0] = m[mt][1] = -1e30f; l[mt][0] = l[mt][1] = 0.f; }
    float oacc[2][8][4];
#pragma unroll
    for (int mt = 0; mt < 2; mt++)
#pragma unroll
        for (int j = 0; j < 8; j++)
#pragma unroll
            for (int i = 0; i < 4; i++) oacc[mt][j][i] = 0.f;

    const int NIT = SEQ / KCH;   // 32

    for (int it = 0; it < NIT; it++) {
        const int buf = it & 1;
        CP_WAIT(0);
        __syncthreads();
        if (it + 1 < NIT) ISSUE_KV((it + 1) * KCH, buf ^ 1);

        const uint32_t sk = smem_u32(Ks) + buf * bufstride;
        const uint32_t sv = smem_u32(Vs) + buf * bufstride;

        float s[2][8][4];
#pragma unroll
        for (int mt = 0; mt < 2; mt++)
#pragma unroll
            for (int j = 0; j < 8; j++)
#pragma unroll
                for (int i = 0; i < 4; i++) s[mt][j][i] = 0.f;

#pragma unroll
        for (int ks = 0; ks < 4; ks++) {
            const int k0 = ks * 16;
            uint32_t af[2][4];
#pragma unroll
            for (int mt = 0; mt < 2; mt++)
                ldsm4(af[mt], qbase_s + ((qr0 + mt * 16) * ASTRH + k0) * 2 + laneA);
#pragma unroll
            for (int jp = 0; jp < 4; jp++) {
                uint32_t bf[4];
                ldsm4(bf, sk + ((jp * 16) * ASTRH + k0) * 2 + laneB);
#pragma unroll
                for (int mt = 0; mt < 2; mt++) {
                    MMA_F16(s[mt][2 * jp],     af[mt], bf[0], bf[1]);
                    MMA_F16(s[mt][2 * jp + 1], af[mt], bf[2], bf[3]);
                }
            }
        }

        uint32_t pa01[2][8], pa23[2][8];
#pragma unroll
        for (int mt = 0; mt < 2; mt++) {
            // pairwise max tree (fewer dependent fmax ops)
            float a01 = fmaxf(fmaxf(s[mt][0][0], s[mt][0][1]), fmaxf(s[mt][1][0], s[mt][1][1]));
            float b01 = fmaxf(fmaxf(s[mt][2][0], s[mt][2][1]), fmaxf(s[mt][3][0], s[mt][3][1]));
            float c01 = fmaxf(fmaxf(s[mt][4][0], s[mt][4][1]), fmaxf(s[mt][5][0], s[mt][5][1]));
            float d01 = fmaxf(fmaxf(s[mt][6][0], s[mt][6][1]), fmaxf(s[mt][7][0], s[mt][7][1]));
            float mx0 = fmaxf(fmaxf(a01, b01), fmaxf(c01, d01));
            float a23 = fmaxf(fmaxf(s[mt][0][2], s[mt][0][3]), fmaxf(s[mt][1][2], s[mt][1][3]));
            float b23 = fmaxf(fmaxf(s[mt][2][2], s[mt][2][3]), fmaxf(s[mt][3][2], s[mt][3][3]));
            float c23 = fmaxf(fmaxf(s[mt][4][2], s[mt][4][3]), fmaxf(s[mt][5][2], s[mt][5][3]));
            float d23 = fmaxf(fmaxf(s[mt][6][2], s[mt][6][3]), fmaxf(s[mt][7][2], s[mt][7][3]));
            float mx1 = fmaxf(fmaxf(a23, b23), fmaxf(c23, d23));
            mx0 = fmaxf(mx0, __shfl_xor_sync(0xffffffffu, mx0, 1));
            mx0 = fmaxf(mx0, __shfl_xor_sync(0xffffffffu, mx0, 2));
            mx1 = fmaxf(mx1, __shfl_xor_sync(0xffffffffu, mx1, 1));
            mx1 = fmaxf(mx1, __shfl_xor_sync(0xffffffffu, mx1, 2));

            const float m0n = fmaxf(m[mt][0], mx0);
            const float m1n = fmaxf(m[mt][1], mx1);
            const float a0 = ex2a(m[mt][0] - m0n);
            const float a1 = ex2a(m[mt][1] - m1n);
            m[mt][0] = m0n; m[mt][1] = m1n;

            float rs0 = 0.f, rs1 = 0.f;
#pragma unroll
            for (int j = 0; j < 8; j++) {
                float p0 = ex2a(s[mt][j][0] - m0n);
                float p1 = ex2a(s[mt][j][1] - m0n);
                float p2 = ex2a(s[mt][j][2] - m1n);
                float p3 = ex2a(s[mt][j][3] - m1n);
                rs0 += p0 + p1;
                rs1 += p2 + p3;
                __half2 h01 = __floats2half2_rn(p0, p1);
                __half2 h23 = __floats2half2_rn(p2, p3);
                pa01[mt][j] = *reinterpret_cast<uint32_t*>(&h01);
                pa23[mt][j] = *reinterpret_cast<uint32_t*>(&h23);
            }
            rs0 += __shfl_xor_sync(0xffffffffu, rs0, 1);
            rs0 += __shfl_xor_sync(0xffffffffu, rs0, 2);
            rs1 += __shfl_xor_sync(0xffffffffu, rs1, 1);
            rs1 += __shfl_xor_sync(0xffffffffu, rs1, 2);
            l[mt][0] = l[mt][0] * a0 + rs0;
            l[mt][1] = l[mt][1] * a1 + rs1;
#pragma unroll
            for (int j = 0; j < 8; j++) {
                oacc[mt][j][0] *= a0; oacc[mt][j][1] *= a0;
                oacc[mt][j][2] *= a1; oacc[mt][j][3] *= a1;
            }
        }

#pragma unroll
        for (int ks = 0; ks < 4; ks++) {
            const int k0 = ks * 16;
            uint32_t paf[2][4];
#pragma unroll
            for (int mt = 0; mt < 2; mt++) {
                paf[mt][0] = pa01[mt][2 * ks];
                paf[mt][1] = pa23[mt][2 * ks];
                paf[mt][2] = pa01[mt][2 * ks + 1];
                paf[mt][3] = pa23[mt][2 * ks + 1];
            }
#pragma unroll
            for (int jp = 0; jp < 4; jp++) {
                uint32_t bf[4];
                ldsm4t(bf, sv + (k0 * ASTRH + jp * 16) * 2 + laneA);
#pragma unroll
                for (int mt = 0; mt < 2; mt++) {
                    MMA_F16(oacc[mt][2 * jp],     paf[mt], bf[0], bf[1]);
                    MMA_F16(oacc[mt][2 * jp + 1], paf[mt], bf[2], bf[3]);
                }
            }
        }
    }
#undef ISSUE_KV

    const int lq  = lane >> 2;
    const int lr4 = lane & 3;
#pragma unroll
    for (int mt = 0; mt < 2; mt++) {
        const float inv0 = 1.f / l[mt][0];
        const float inv1 = 1.f / l[mt][1];
        const size_t row0 = (size_t)b * SEQ + qbase + qr0 + mt * 16 + lq;
#pragma unroll
        for (int j = 0; j < 8; j++) {
            const int col = hbase + j * 8 + 2 * lr4;
            *reinterpret_cast<__half2*>(&g_Oh[row0 * DMODEL + col]) =
                __floats2half2_rn(oacc[mt][j][0] * inv0, oacc[mt][j][1] * inv0);
            *reinterpret_cast<__half2*>(&g_Oh[(row0 + 8) * DMODEL + col]) =
                __floats2half2_rn(oacc[mt][j][2] * inv1, oacc[mt][j][3] * inv1);
        }
    }
}

// ---------------------------------------------------------------------------
// launch
// ---------------------------------------------------------------------------
extern "C" void kernel_launch(void* const* d_in, const int* in_sizes, int n_in,
                              void* d_out, int out_size)
{
    const float* q   = (const float*)d_in[0];
    const float* k   = (const float*)d_in[1];
    const float* v   = (const float*)d_in[2];
    const float* W_q = (const float*)d_in[3];
    const float* b_q = (const float*)d_in[4];
    const float* W_k = (const float*)d_in[5];
    const float* b_k = (const float*)d_in[6];
    const float* W_v = (const float*)d_in[7];
    const float* b_v = (const float*)d_in[8];
    const float* W_o = (const float*)d_in[9];
    const float* b_o = (const float*)d_in[10];
    float* out = (float*)d_out;

    prepass<<<dim3(1024, 7), 256>>>(q, k, v, W_q, W_k, W_v, W_o);

    cudaFuncSetAttribute(gemm_qkv, cudaFuncAttributeMaxDynamicSharedMemorySize, GEMM_SMEM);
    cudaFuncSetAttribute(gemm_out, cudaFuncAttributeMaxDynamicSharedMemorySize, GEMM_SMEM);
    dim3 qkvgrid(DMODEL / GBN, MROWS / GBM, 3);   // (8, 32, 3)
    gemm_qkv<<<qkvgrid, 256, GEMM_SMEM>>>(b_q, b_k, b_v);

    cudaFuncSetAttribute(attn_f16, cudaFuncAttributeMaxDynamicSharedMemorySize, ATTN_SMEM);
    dim3 agrid(SEQ / QT, NHEADS, BATCH);   // (16, 16, 2)
    attn_f16<<<agrid, dim3(128), ATTN_SMEM>>>();

    dim3 ogrid(DMODEL / GBN, MROWS / GBM);  // (8, 32)
    gemm_out<<<ogrid, 256, GEMM_SMEM>>>(b_o, out);
    (void)in_sizes; (void)n_in; (void)out_size;
}

// round 15
// speedup vs baseline: 1.1704x; 1.1704x over previous
#include <cuda_runtime.h>
#include <cuda_fp16.h>
#include <cstdint>
#include <math.h>

#define BATCH 2
#define SEQ   2048
#define DMODEL 1024
#define NHEADS 16
#define DK    64
#define MROWS (BATCH*SEQ)   // 4096

// ---------------------------------------------------------------------------
// Scratch (fp16 operands + intermediates)
// ---------------------------------------------------------------------------
__device__ __align__(128) __half g_Qh[MROWS * DMODEL];
__device__ __align__(128) __half g_Kh[MROWS * DMODEL];
__device__ __align__(128) __half g_Vh[MROWS * DMODEL];
__device__ __align__(128) __half g_Oh[MROWS * DMODEL];
__device__ __align__(128) __half g_Xq[MROWS * DMODEL];
__device__ __align__(128) __half g_Xk[MROWS * DMODEL];
__device__ __align__(128) __half g_Xv[MROWS * DMODEL];
__device__ __align__(128) __half g_Wq[DMODEL * DMODEL];
__device__ __align__(128) __half g_Wk[DMODEL * DMODEL];
__device__ __align__(128) __half g_Wv[DMODEL * DMODEL];
__device__ __align__(128) __half g_Wo[DMODEL * DMODEL];

__device__ __forceinline__ uint32_t smem_u32(const void* p) {
    uint32_t a;
    asm("{ .reg .u64 t; cvta.to.shared.u64 t, %1; cvt.u32.u64 %0, t; }" : "=r"(a) : "l"(p));
    return a;
}
__device__ __forceinline__ void cp16(uint32_t dst, const void* src) {
    asm volatile("cp.async.cg.shared.global [%0], [%1], 16;" :: "r"(dst), "l"(src));
}
#define CP_COMMIT() asm volatile("cp.async.commit_group;" ::: "memory")
#define CP_WAIT(n)  asm volatile("cp.async.wait_group %0;" :: "n"(n) : "memory")

__device__ __forceinline__ void ldsm4(uint32_t* r, uint32_t a) {
    asm volatile("ldmatrix.sync.aligned.m8n8.x4.shared.b16 {%0,%1,%2,%3}, [%4];"
        : "=r"(r[0]), "=r"(r[1]), "=r"(r[2]), "=r"(r[3]) : "r"(a));
}
__device__ __forceinline__ void ldsm4t(uint32_t* r, uint32_t a) {
    asm volatile("ldmatrix.sync.aligned.m8n8.x4.trans.shared.b16 {%0,%1,%2,%3}, [%4];"
        : "=r"(r[0]), "=r"(r[1]), "=r"(r[2]), "=r"(r[3]) : "r"(a));
}
__device__ __forceinline__ float ex2a(float x) {
    float y; asm("ex2.approx.ftz.f32 %0, %1;" : "=f"(y) : "f"(x));
    return y;
}
#define MMA_F16(d, a, b0, b1) \
    asm volatile( \
        "mma.sync.aligned.m16n8k16.row.col.f32.f16.f16.f32 " \
        "{%0,%1,%2,%3}, {%4,%5,%6,%7}, {%8,%9}, {%0,%1,%2,%3};" \
        : "+f"((d)[0]), "+f"((d)[1]), "+f"((d)[2]), "+f"((d)[3]) \
        : "r"((a)[0]), "r"((a)[1]), "r"((a)[2]), "r"((a)[3]), "r"(b0), "r"(b1))

// Q pre-scale: 1/sqrt(64) * log2(e)  (softmax in base 2)
#define QSCALE (0.125f * 1.44269504088896f)

// ---------------------------------------------------------------------------
// Pre-pass: fp32 -> fp16 (rn) into scratch (inputs + weights).
// ---------------------------------------------------------------------------
__global__ __launch_bounds__(256) void prepass(
    const float* __restrict__ q, const float* __restrict__ k, const float* __restrict__ v,
    const float* __restrict__ Wq, const float* __restrict__ Wk,
    const float* __restrict__ Wv, const float* __restrict__ Wo)
{
    const float* src; __half* dst; int n8;
    switch (blockIdx.y) {
        case 0: src = q;  dst = g_Xq; n8 = MROWS * DMODEL / 8; break;
        case 1: src = k;  dst = g_Xk; n8 = MROWS * DMODEL / 8; break;
        case 2: src = v;  dst = g_Xv; n8 = MROWS * DMODEL / 8; break;
        case 3: src = Wq; dst = g_Wq; n8 = DMODEL * DMODEL / 8; break;
        case 4: src = Wk; dst = g_Wk; n8 = DMODEL * DMODEL / 8; break;
        case 5: src = Wv; dst = g_Wv; n8 = DMODEL * DMODEL / 8; break;
        default: src = Wo; dst = g_Wo; n8 = DMODEL * DMODEL / 8; break;
    }
    for (int i = blockIdx.x * blockDim.x + threadIdx.x; i < n8; i += gridDim.x * blockDim.x) {
        float4 t0 = reinterpret_cast<const float4*>(src)[2 * i];
        float4 t1 = reinterpret_cast<const float4*>(src)[2 * i + 1];
        uint4 u;
        __half2 h;
        h = __floats2half2_rn(t0.x, t0.y); u.x = *reinterpret_cast<uint32_t*>(&h);
        h = __floats2half2_rn(t0.z, t0.w); u.y = *reinterpret_cast<uint32_t*>(&h);
        h = __floats2half2_rn(t1.x, t1.y); u.z = *reinterpret_cast<uint32_t*>(&h);
        h = __floats2half2_rn(t1.z, t1.w); u.w = *reinterpret_cast<uint32_t*>(&h);
        reinterpret_cast<uint4*>(dst)[i] = u;
    }
}

// ---------------------------------------------------------------------------
// FP16 mma GEMM (NT) — exact R10 shape: 3-stage, CP_WAIT(1), late issue.
// CTA 128x128, 8 warps of 64x32, K-chunk 32, ldmatrix.
// mode: 0 = fp32 out, 1 = fp16 out, 2 = fp16 out * QSCALE
// ---------------------------------------------------------------------------
#define GBM 128
#define GBN 128
#define GBK 32
#define GSTR 40
#define GTILE_H (128 * GSTR)
#define GSTG 3
#define GEMM_SMEM (GSTG * 2 * GTILE_H * 2)  // 61440 B

__device__ __forceinline__ void gemm_f16_body(
    const __half* __restrict__ A, const __half* __restrict__ B,
    const float* __restrict__ bias, float* __restrict__ Cf, __half* __restrict__ Ch,
    int mode)
{
    extern __shared__ __half smh[];
    __half* As = smh;
    __half* Bs = smh + GSTG * GTILE_H;

    const int t    = threadIdx.x;
    const int wid  = t >> 5;
    const int lane = t & 31;
    const int l7   = lane & 7;
    const int l8   = (lane >> 3) & 1;
    const int l16  = lane >> 4;
    const int lq   = lane >> 2;
    const int lr4  = lane & 3;
    const int mbase = blockIdx.y * GBM;
    const int nbase = blockIdx.x * GBN;

    const int srow = t >> 1, sseg = (t & 1) * 16;
    const __half* Ap = A + (size_t)(mbase + srow) * DMODEL + sseg;
    const __half* Bp = B + (size_t)(nbase + srow) * DMODEL + sseg;
    const uint32_t a_s = smem_u32(As) + (srow * GSTR + sseg) * 2;
    const uint32_t b_s = smem_u32(Bs) + (srow * GSTR + sseg) * 2;
    const uint32_t stb = GTILE_H * 2;

#define GI(c, s) { const __half* ap_ = Ap + (c) * GBK; \
        cp16(a_s + (s) * stb, ap_); cp16(a_s + (s) * stb + 16, ap_ + 8); \
        const __half* bp_ = Bp + (c) * GBK; \
        cp16(b_s + (s) * stb, bp_); cp16(b_s + (s) * stb + 16, bp_ + 8); }

    GI(0, 0); CP_COMMIT();
    GI(1, 1); CP_COMMIT();

    const int rm = (wid & 1) * 64;
    const int cn = (wid >> 1) * 32;
    const uint32_t laneA = ((l7 + 8 * l8) * GSTR + 8 * l16) * 2;
    const uint32_t laneB = ((l7 + 8 * l16) * GSTR + 8 * l8) * 2;

    float acc[4][4][4];
#pragma unroll
    for (int mt = 0; mt < 4; mt++)
#pragma unroll
        for (int nt = 0; nt < 4; nt++)
#pragma unroll
            for (int i = 0; i < 4; i++) acc[mt][nt][i] = 0.f;

    const int NCH = DMODEL / GBK;   // 32

    for (int c = 0; c < NCH; c++) {
        CP_WAIT(1);
        __syncthreads();
        const uint32_t sa = smem_u32(As) + (c % GSTG) * stb;
        const uint32_t sb = smem_u32(Bs) + (c % GSTG) * stb;
#pragma unroll
        for (int ks = 0; ks < 2; ks++) {
            const int k0 = ks * 16;
            uint32_t af[4][4], bf[2][4];
#pragma unroll
            for (int mt = 0; mt < 4; mt++)
                ldsm4(af[mt], sa + ((rm + mt * 16) * GSTR + k0) * 2 + laneA);
#pragma unroll
            for (int p = 0; p < 2; p++)
                ldsm4(bf[p], sb + ((cn + p * 16) * GSTR + k0) * 2 + laneB);
#pragma unroll
            for (int mt = 0; mt < 4; mt++)
#pragma unroll
                for (int nt = 0; nt < 4; nt++)
                    MMA_F16(acc[mt][nt], af[mt], bf[nt >> 1][(nt & 1) * 2],
                            bf[nt >> 1][(nt & 1) * 2 + 1]);
        }
        if (c + 2 < NCH) { GI(c + 2, (c + 2) % GSTG); }
        CP_COMMIT();
    }
#undef GI

#pragma unroll
    for (int mt = 0; mt < 4; mt++) {
        const int r0 = mbase + rm + mt * 16 + lq;
#pragma unroll
        for (int nt = 0; nt < 4; nt++) {
            const int col = nbase + cn + nt * 8 + lr4 * 2;
            const float bz0 = bias[col], bz1 = bias[col + 1];
            float v00 = acc[mt][nt][0] + bz0, v01 = acc[mt][nt][1] + bz1;
            float v10 = acc[mt][nt][2] + bz0, v11 = acc[mt][nt][3] + bz1;
            if (mode == 0) {
                *reinterpret_cast<float2*>(&Cf[(size_t)r0 * DMODEL + col]) = make_float2(v00, v01);
                *reinterpret_cast<float2*>(&Cf[(size_t)(r0 + 8) * DMODEL + col]) = make_float2(v10, v11);
            } else {
                if (mode == 2) { v00 *= QSCALE; v01 *= QSCALE; v10 *= QSCALE; v11 *= QSCALE; }
                *reinterpret_cast<__half2*>(&Ch[(size_t)r0 * DMODEL + col]) = __floats2half2_rn(v00, v01);
                *reinterpret_cast<__half2*>(&Ch[(size_t)(r0 + 8) * DMODEL + col]) = __floats2half2_rn(v10, v11);
            }
        }
    }
}

__global__ __launch_bounds__(256, 2) void gemm_qkv(
    const float* __restrict__ bq, const float* __restrict__ bk, const float* __restrict__ bv)
{
    const int z = blockIdx.z;
    const __half* A = (z == 0) ? g_Xq : (z == 1) ? g_Xk : g_Xv;
    const __half* B = (z == 0) ? g_Wq : (z == 1) ? g_Wk : g_Wv;
    const float* bi = (z == 0) ? bq   : (z == 1) ? bk   : bv;
    __half* C      = (z == 0) ? g_Qh : (z == 1) ? g_Kh : g_Vh;
    gemm_f16_body(A, B, bi, nullptr, C, (z == 0) ? 2 : 1);
}

__global__ __launch_bounds__(256, 2) void gemm_out(
    const float* __restrict__ bo, float* __restrict__ out)
{
    gemm_f16_body(g_Oh, g_Wo, bo, out, nullptr, 0);
}

// ---------------------------------------------------------------------------
// FP16 flash attention, P in registers, triple-buffered KV.
// grid (16,16,2), block 128 (4 warps x 32 q-rows), 3 CTAs/SM (221KB smem).
// ---------------------------------------------------------------------------
#define QT  128
#define KCH 64
#define ASTRH 72
#define AQ_OFF 0
#define AK_OFF (QT * ASTRH)
#define AV_OFF (AK_OFF + 3 * KCH * ASTRH)
#define ATTN_SMEM ((QT * ASTRH + 6 * KCH * ASTRH) * 2)  // 73728 B

__global__ __launch_bounds__(128, 3) void attn_f16()
{
    extern __shared__ __half sh[];
    __half* Qs = sh + AQ_OFF;
    __half* Ks = sh + AK_OFF;
    __half* Vs = sh + AV_OFF;

    const int t    = threadIdx.x;
    const int wid  = t >> 5;
    const int lane = t & 31;
    const int l7   = lane & 7;
    const int l8   = (lane >> 3) & 1;
    const int l16  = lane >> 4;

    const int qbase = blockIdx.x * QT;
    const int h     = blockIdx.y;
    const int b     = blockIdx.z;
    const int hbase = h * DK;

    const int klr = t >> 1;
    const int klc = (t & 1) * 32;
    const uint32_t kvoff = (klr * ASTRH + klc) * 2;
    const uint32_t bufstride = KCH * ASTRH * 2;

#define ISSUE_KV(j0, buf) { \
        const size_t g_ = ((size_t)b * SEQ + (j0) + klr) * DMODEL + hbase + klc; \
        const __half* ks_ = g_Kh + g_; const __half* vs_ = g_Vh + g_; \
        const uint32_t kd_ = smem_u32(Ks) + (buf) * bufstride + kvoff; \
        const uint32_t vd_ = smem_u32(Vs) + (buf) * bufstride + kvoff; \
        cp16(kd_, ks_); cp16(kd_ + 16, ks_ + 8); cp16(kd_ + 32, ks_ + 16); cp16(kd_ + 48, ks_ + 24); \
        cp16(vd_, vs_); cp16(vd_ + 16, vs_ + 8); cp16(vd_ + 32, vs_ + 16); cp16(vd_ + 48, vs_ + 24); \
        CP_COMMIT(); }

    // prologue: Q + KV chunk 0 in one group, KV chunk 1 in a second group
    {
        const __half* src = g_Qh + ((size_t)b * SEQ + qbase + t) * DMODEL + hbase;
        const uint32_t dst = smem_u32(Qs) + t * ASTRH * 2;
#pragma unroll
        for (int i = 0; i < 8; i++) cp16(dst + i * 16, src + i * 8);
    }
    ISSUE_KV(0, 0);        // commits {Q, KV0}
    ISSUE_KV(KCH, 1);      // commits {KV1}

    const int qr0 = wid * 32;
    const uint32_t laneA = ((l7 + 8 * l8) * ASTRH + 8 * l16) * 2;
    const uint32_t laneB = ((l7 + 8 * l16) * ASTRH + 8 * l8) * 2;
    const uint32_t qbase_s = smem_u32(Qs);

    float m[2][2], l[2][2];
#pragma unroll
    for (int mt = 0; mt < 2; mt++) { m[mt][0] = m[mt][1] = -1e30f; l[mt][0] = l[mt][1] = 0.f; }
    float oacc[2][8][4];
#pragma unroll
    for (int mt = 0; mt < 2; mt++)
#pragma unroll
        for (int j = 0; j < 8; j++)
#pragma unroll
            for (int i = 0; i < 4; i++) oacc[mt][j][i] = 0.f;

    const int NIT = SEQ / KCH;   // 32

    for (int it = 0; it < NIT; it++) {
        const int buf = it % 3;
        CP_WAIT(1);            // chunk `it` complete; `it+1` may be in flight
        __syncthreads();       // also orders iter it-1 reads before new writes
        if (it + 2 < NIT) ISSUE_KV((it + 2) * KCH, (it + 2) % 3);

        const uint32_t sk = smem_u32(Ks) + buf * bufstride;
        const uint32_t sv = smem_u32(Vs) + buf * bufstride;

        // S = Q K^T
        float s[2][8][4];
#pragma unroll
        for (int mt = 0; mt < 2; mt++)
#pragma unroll
            for (int j = 0; j < 8; j++)
#pragma unroll
                for (int i = 0; i < 4; i++) s[mt][j][i] = 0.f;

#pragma unroll
        for (int ks = 0; ks < 4; ks++) {
            const int k0 = ks * 16;
            uint32_t af[2][4];
#pragma unroll
            for (int mt = 0; mt < 2; mt++)
                ldsm4(af[mt], qbase_s + ((qr0 + mt * 16) * ASTRH + k0) * 2 + laneA);
#pragma unroll
            for (int jp = 0; jp < 4; jp++) {
                uint32_t bf[4];
                ldsm4(bf, sk + ((jp * 16) * ASTRH + k0) * 2 + laneB);
#pragma unroll
                for (int mt = 0; mt < 2; mt++) {
                    MMA_F16(s[mt][2 * jp],     af[mt], bf[0], bf[1]);
                    MMA_F16(s[mt][2 * jp + 1], af[mt], bf[2], bf[3]);
                }
            }
        }

        // softmax (base 2, fp32 ex2), P packed into A-fragments (registers)
        uint32_t pa01[2][8], pa23[2][8];
#pragma unroll
        for (int mt = 0; mt < 2; mt++) {
            float a01 = fmaxf(fmaxf(s[mt][0][0], s[mt][0][1]), fmaxf(s[mt][1][0], s[mt][1][1]));
            float b01 = fmaxf(fmaxf(s[mt][2][0], s[mt][2][1]), fmaxf(s[mt][3][0], s[mt][3][1]));
            float c01 = fmaxf(fmaxf(s[mt][4][0], s[mt][4][1]), fmaxf(s[mt][5][0], s[mt][5][1]));
            float d01 = fmaxf(fmaxf(s[mt][6][0], s[mt][6][1]), fmaxf(s[mt][7][0], s[mt][7][1]));
            float mx0 = fmaxf(fmaxf(a01, b01), fmaxf(c01, d01));
            float a23 = fmaxf(fmaxf(s[mt][0][2], s[mt][0][3]), fmaxf(s[mt][1][2], s[mt][1][3]));
            float b23 = fmaxf(fmaxf(s[mt][2][2], s[mt][2][3]), fmaxf(s[mt][3][2], s[mt][3][3]));
            float c23 = fmaxf(fmaxf(s[mt][4][2], s[mt][4][3]), fmaxf(s[mt][5][2], s[mt][5][3]));
            float d23 = fmaxf(fmaxf(s[mt][6][2], s[mt][6][3]), fmaxf(s[mt][7][2], s[mt][7][3]));
            float mx1 = fmaxf(fmaxf(a23, b23), fmaxf(c23, d23));
            mx0 = fmaxf(mx0, __shfl_xor_sync(0xffffffffu, mx0, 1));
            mx0 = fmaxf(mx0, __shfl_xor_sync(0xffffffffu, mx0, 2));
            mx1 = fmaxf(mx1, __shfl_xor_sync(0xffffffffu, mx1, 1));
            mx1 = fmaxf(mx1, __shfl_xor_sync(0xffffffffu, mx1, 2));

            const float m0n = fmaxf(m[mt][0], mx0);
            const float m1n = fmaxf(m[mt][1], mx1);
            const float a0 = ex2a(m[mt][0] - m0n);
            const float a1 = ex2a(m[mt][1] - m1n);
            m[mt][0] = m0n; m[mt][1] = m1n;

            float rs0 = 0.f, rs1 = 0.f;
#pragma unroll
            for (int j = 0; j < 8; j++) {
                float p0 = ex2a(s[mt][j][0] - m0n);
                float p1 = ex2a(s[mt][j][1] - m0n);
                float p2 = ex2a(s[mt][j][2] - m1n);
                float p3 = ex2a(s[mt][j][3] - m1n);
                rs0 += p0 + p1;
                rs1 += p2 + p3;
                __half2 h01 = __floats2half2_rn(p0, p1);
                __half2 h23 = __floats2half2_rn(p2, p3);
                pa01[mt][j] = *reinterpret_cast<uint32_t*>(&h01);
                pa23[mt][j] = *reinterpret_cast<uint32_t*>(&h23);
            }
            rs0 += __shfl_xor_sync(0xffffffffu, rs0, 1);
            rs0 += __shfl_xor_sync(0xffffffffu, rs0, 2);
            rs1 += __shfl_xor_sync(0xffffffffu, rs1, 1);
            rs1 += __shfl_xor_sync(0xffffffffu, rs1, 2);
            l[mt][0] = l[mt][0] * a0 + rs0;
            l[mt][1] = l[mt][1] * a1 + rs1;
#pragma unroll
            for (int j = 0; j < 8; j++) {
                oacc[mt][j][0] *= a0; oacc[mt][j][1] *= a0;
                oacc[mt][j][2] *= a1; oacc[mt][j][3] *= a1;
            }
        }

        // O += P V  (P from registers; V via ldmatrix.trans)
#pragma unroll
        for (int ks = 0; ks < 4; ks++) {
            const int k0 = ks * 16;
            uint32_t paf[2][4];
#pragma unroll
            for (int mt = 0; mt < 2; mt++) {
                paf[mt][0] = pa01[mt][2 * ks];
                paf[mt][1] = pa23[mt][2 * ks];
                paf[mt][2] = pa01[mt][2 * ks + 1];
                paf[mt][3] = pa23[mt][2 * ks + 1];
            }
#pragma unroll
            for (int jp = 0; jp < 4; jp++) {
                uint32_t bf[4];
                ldsm4t(bf, sv + (k0 * ASTRH + jp * 16) * 2 + laneA);
#pragma unroll
                for (int mt = 0; mt < 2; mt++) {
                    MMA_F16(oacc[mt][2 * jp],     paf[mt], bf[0], bf[1]);
                    MMA_F16(oacc[mt][2 * jp + 1], paf[mt], bf[2], bf[3]);
                }
            }
        }
    }
#undef ISSUE_KV

    // finalize -> fp16 O
    const int lq  = lane >> 2;
    const int lr4 = lane & 3;
#pragma unroll
    for (int mt = 0; mt < 2; mt++) {
        const float inv0 = 1.f / l[mt][0];
        const float inv1 = 1.f / l[mt][1];
        const size_t row0 = (size_t)b * SEQ + qbase + qr0 + mt * 16 + lq;
#pragma unroll
        for (int j = 0; j < 8; j++) {
            const int col = hbase + j * 8 + 2 * lr4;
            *reinterpret_cast<__half2*>(&g_Oh[row0 * DMODEL + col]) =
                __floats2half2_rn(oacc[mt][j][0] * inv0, oacc[mt][j][1] * inv0);
            *reinterpret_cast<__half2*>(&g_Oh[(row0 + 8) * DMODEL + col]) =
                __floats2half2_rn(oacc[mt][j][2] * inv1, oacc[mt][j][3] * inv1);
        }
    }
}

// ---------------------------------------------------------------------------
// launch
// ---------------------------------------------------------------------------
extern "C" void kernel_launch(void* const* d_in, const int* in_sizes, int n_in,
                              void* d_out, int out_size)
{
    const float* q   = (const float*)d_in[0];
    const float* k   = (const float*)d_in[1];
    const float* v   = (const float*)d_in[2];
    const float* W_q = (const float*)d_in[3];
    const float* b_q = (const float*)d_in[4];
    const float* W_k = (const float*)d_in[5];
    const float* b_k = (const float*)d_in[6];
    const float* W_v = (const float*)d_in[7];
    const float* b_v = (const float*)d_in[8];
    const float* W_o = (const float*)d_in[9];
    const float* b_o = (const float*)d_in[10];
    float* out = (float*)d_out;

    prepass<<<dim3(1024, 7), 256>>>(q, k, v, W_q, W_k, W_v, W_o);

    cudaFuncSetAttribute(gemm_qkv, cudaFuncAttributeMaxDynamicSharedMemorySize, GEMM_SMEM);
    cudaFuncSetAttribute(gemm_out, cudaFuncAttributeMaxDynamicSharedMemorySize, GEMM_SMEM);
    dim3 qkvgrid(DMODEL / GBN, MROWS / GBM, 3);   // (8, 32, 3)
    gemm_qkv<<<qkvgrid, 256, GEMM_SMEM>>>(b_q, b_k, b_v);

    cudaFuncSetAttribute(attn_f16, cudaFuncAttributeMaxDynamicSharedMemorySize, ATTN_SMEM);
    dim3 agrid(SEQ / QT, NHEADS, BATCH);   // (16, 16, 2)
    attn_f16<<<agrid, dim3(128), ATTN_SMEM>>>();

    dim3 ogrid(DMODEL / GBN, MROWS / GBM);  // (8, 32)
    gemm_out<<<ogrid, 256, GEMM_SMEM>>>(b_o, out);
    (void)in_sizes; (void)n_in; (void)out_size;
}